// round 16
// baseline (speedup 1.0000x reference)
#include <cuda_runtime.h>
#include <cstdint>

#define CIN    32
#define COUT   64
#define KOFF   27
#define TILE   64       // pairs per block
#define APITCH 36       // raw A row pitch (floats)
#define DPITCH 72       // D bounce-buffer pitch (floats; 288B rows, 16B-aligned)

__device__ __forceinline__ uint32_t pack_bf16x2(float lo, float hi) {
    uint32_t r;
    asm("cvt.rn.bf16x2.f32 %0, %1, %2;" : "=r"(r) : "f"(hi), "f"(lo));
    return r;
}
__device__ __forceinline__ void split_bf16(float x, float y,
                                           uint32_t& h, uint32_t& l) {
    h = pack_bf16x2(x, y);
    float xh = __uint_as_float(h << 16);
    float yh = __uint_as_float(h & 0xFFFF0000u);
    l = pack_bf16x2(x - xh, y - yh);
}

#define MMA_BF16(D, A0, A1, A2, A3, B0, B1)                                   \
    asm volatile(                                                             \
        "mma.sync.aligned.m16n8k16.row.col.f32.bf16.bf16.f32 "                \
        "{%0,%1,%2,%3}, {%4,%5,%6,%7}, {%8,%9}, {%0,%1,%2,%3};"               \
        : "+f"(D[0]), "+f"(D[1]), "+f"(D[2]), "+f"(D[3])                      \
        : "r"(A0), "r"(A1), "r"(A2), "r"(A3), "r"(B0), "r"(B1))

// ---------------------------------------------------------------------------
// bf16 HMMA sparse conv, 3-term compensation (R15-verified math + TMA reduce),
// with the TMA scatter PIPELINED per 16-pair M-block so the async engine
// drains during subsequent math instead of in a serial tail.
// ---------------------------------------------------------------------------
__global__ __launch_bounds__(128, 6) void conv_tc_kernel(
    const float* __restrict__ feats,
    const float* __restrict__ W,
    const int*   __restrict__ in_idx,
    const int*   __restrict__ out_idx,
    float*       __restrict__ out,
    int M, int kBase)
{
    __shared__ __align__(16) float A_raw[TILE][APITCH];
    __shared__ __align__(16) float D_s[TILE][DPITCH];
    __shared__ int okv_s[TILE];

    const int tid  = threadIdx.x;
    const int wid  = tid >> 5;
    const int lane = tid & 31;
    const int gid  = lane >> 2;
    const int q    = lane & 3;
    const int k    = kBase + (int)blockIdx.y;
    const size_t kM = (size_t)k * M;

    // ---- B fragments (W[k] hi/lo, bf16) : verified ----
    uint32_t Bh[2][2][2], Bl[2][2][2];
    {
        const float* Wk = W + (size_t)k * (CIN * COUT);
        #pragma unroll
        for (int t = 0; t < 2; ++t) {
            const int n = (2 * wid + t) * 8 + gid;
            #pragma unroll
            for (int kb = 0; kb < 2; ++kb) {
                const int r0 = kb * 16 + 2 * q;
                float w0 = Wk[(r0    ) * COUT + n];
                float w1 = Wk[(r0 + 1) * COUT + n];
                float w2 = Wk[(r0 + 8) * COUT + n];
                float w3 = Wk[(r0 + 9) * COUT + n];
                split_bf16(w0, w1, Bh[t][kb][0], Bl[t][kb][0]);
                split_bf16(w2, w3, Bh[t][kb][1], Bl[t][kb][1]);
            }
        }
    }

    const int tileBase = (int)blockIdx.x * TILE;
    if (tileBase >= M) return;
    const int nv = (M - tileBase < TILE) ? (M - tileBase) : TILE;

    // ---- cooperative raw stage (verified) ----
    {
        int ikv = 0;
        const int rloc = 16 * wid + lane;
        if (lane < 16) {
            const bool v = (rloc < nv);
            ikv = v ? in_idx[kM + tileBase + rloc] : 0;
            okv_s[rloc] = v ? out_idx[kM + tileBase + rloc] : 0;
        }
        const int g   = lane >> 3;
        const int sec = lane & 7;
        const float4* fb = reinterpret_cast<const float4*>(feats);
        #pragma unroll
        for (int r = 0; r < 4; ++r) {
            const int rw = 4 * r + g;
            const int ik = __shfl_sync(0xffffffffu, ikv, rw);
            float4 v = fb[(size_t)ik * 8 + sec];
            *reinterpret_cast<float4*>(&A_raw[16 * wid + rw][4 * sec]) = v;
        }
    }
    __syncthreads();

    // ---- math per 16-pair M-block; D_s bounce; PIPELINED TMA scatter ----
    #pragma unroll
    for (int mb = 0; mb < 4; ++mb) {
        if (mb * 16 >= nv) break;
        const int mbase = mb * 16;

        float d[2][4] = {{0.f, 0.f, 0.f, 0.f}, {0.f, 0.f, 0.f, 0.f}};

        #pragma unroll
        for (int kb = 0; kb < 2; ++kb) {
            const int c0 = kb * 16 + 2 * q;
            float2 p0 = *reinterpret_cast<const float2*>(&A_raw[mbase + gid    ][c0    ]);
            float2 p1 = *reinterpret_cast<const float2*>(&A_raw[mbase + gid + 8][c0    ]);
            float2 p2 = *reinterpret_cast<const float2*>(&A_raw[mbase + gid    ][c0 + 8]);
            float2 p3 = *reinterpret_cast<const float2*>(&A_raw[mbase + gid + 8][c0 + 8]);

            uint32_t ah0, ah1, ah2, ah3, al0, al1, al2, al3;
            split_bf16(p0.x, p0.y, ah0, al0);
            split_bf16(p1.x, p1.y, ah1, al1);
            split_bf16(p2.x, p2.y, ah2, al2);
            split_bf16(p3.x, p3.y, ah3, al3);

            #pragma unroll
            for (int t = 0; t < 2; ++t) {
                MMA_BF16(d[t], ah0, ah1, ah2, ah3, Bh[t][kb][0], Bh[t][kb][1]);
                MMA_BF16(d[t], ah0, ah1, ah2, ah3, Bl[t][kb][0], Bl[t][kb][1]);
                MMA_BF16(d[t], al0, al1, al2, al3, Bh[t][kb][0], Bh[t][kb][1]);
            }
        }

        // ---- v4 assembly (verified shfl pairing) -> D_s ----
        #pragma unroll
        for (int t = 0; t < 2; ++t) {
            const int colBase = (2 * wid + t) * 8 + 2 * q;
            #pragma unroll
            for (int ro = 0; ro < 2; ++ro) {
                float x0 = ro ? d[t][2] : d[t][0];
                float x1 = ro ? d[t][3] : d[t][1];
                float y0 = __shfl_xor_sync(0xffffffffu, x0, 1);
                float y1 = __shfl_xor_sync(0xffffffffu, x1, 1);
                const int row = mbase + 8 * ro + gid;
                if ((lane & 1) == 0) {
                    *reinterpret_cast<float4*>(&D_s[row][colBase]) =
                        make_float4(x0, x1, y0, y1);
                }
            }
        }

        // ---- this M-block's rows complete across all warps: issue TMA now ----
        __syncthreads();
        asm volatile("fence.proxy.async.shared::cta;" ::: "memory");
        {
            const int row = mbase + tid;          // tid < 16 handles one row
            if (tid < 16 && row < nv) {
                float* dst = out + (size_t)okv_s[row] * COUT;
                uint32_t saddr = (uint32_t)__cvta_generic_to_shared(&D_s[row][0]);
                asm volatile(
                    "cp.reduce.async.bulk.global.shared::cta.bulk_group.add.f32 "
                    "[%0], [%1], 256;"
                    :: "l"(dst), "r"(saddr) : "memory");
            }
        }
        asm volatile("cp.async.bulk.commit_group;" ::: "memory");
    }

    // Only the last committed group can still be in flight on smem we own.
    asm volatile("cp.async.bulk.wait_group 0;" ::: "memory");
}

// ---------------------------------------------------------------------------
// In-place BatchNorm (inference) + ReLU epilogue, vectorized float4.
// ---------------------------------------------------------------------------
__global__ __launch_bounds__(256) void bn_relu_kernel(
    float* __restrict__ out,
    const float* __restrict__ gamma,
    const float* __restrict__ beta,
    const float* __restrict__ run_mean,
    const float* __restrict__ run_var,
    int n4)
{
    int i = blockIdx.x * blockDim.x + threadIdx.x;
    if (i >= n4) return;

    const int c0 = (i & 15) * 4;
    float4 v = reinterpret_cast<float4*>(out)[i];

    float s0 = gamma[c0 + 0] * rsqrtf(run_var[c0 + 0] + 1e-5f);
    float s1 = gamma[c0 + 1] * rsqrtf(run_var[c0 + 1] + 1e-5f);
    float s2 = gamma[c0 + 2] * rsqrtf(run_var[c0 + 2] + 1e-5f);
    float s3 = gamma[c0 + 3] * rsqrtf(run_var[c0 + 3] + 1e-5f);

    float t0 = beta[c0 + 0] - run_mean[c0 + 0] * s0;
    float t1 = beta[c0 + 1] - run_mean[c0 + 1] * s1;
    float t2 = beta[c0 + 2] - run_mean[c0 + 2] * s2;
    float t3 = beta[c0 + 3] - run_mean[c0 + 3] * s3;

    v.x = fmaxf(fmaf(v.x, s0, t0), 0.0f);
    v.y = fmaxf(fmaf(v.y, s1, t1), 0.0f);
    v.z = fmaxf(fmaf(v.z, s2, t2), 0.0f);
    v.w = fmaxf(fmaf(v.w, s3, t3), 0.0f);

    reinterpret_cast<float4*>(out)[i] = v;
}

// ---------------------------------------------------------------------------
// Launcher: memset(zero) -> 9x conv (3 offsets each; keeps ncu on conv)
//           -> BN+ReLU.
// ---------------------------------------------------------------------------
extern "C" void kernel_launch(void* const* d_in, const int* in_sizes, int n_in,
                              void* d_out, int out_size)
{
    const float* feats    = (const float*)d_in[0];
    const float* W        = (const float*)d_in[1];
    const float* gamma    = (const float*)d_in[2];
    const float* beta     = (const float*)d_in[3];
    const float* run_mean = (const float*)d_in[4];
    const float* run_var  = (const float*)d_in[5];
    const int*   in_idx   = (const int*)d_in[6];
    const int*   out_idx  = (const int*)d_in[7];
    float*       out      = (float*)d_out;

    const int KM = in_sizes[6];
    const int M  = KM / KOFF;

    cudaMemsetAsync(d_out, 0, (size_t)out_size * sizeof(float), 0);

    const int gx = (M + TILE - 1) / TILE;
    for (int kb = 0; kb < KOFF; kb += 3) {
        dim3 grid(gx, 3);
        conv_tc_kernel<<<grid, 128>>>(feats, W, in_idx, out_idx, out, M, kb);
    }

    const int n4 = out_size / 4;
    bn_relu_kernel<<<(n4 + 255) / 256, 256>>>(out, gamma, beta, run_mean, run_var, n4);
}

// round 17
// speedup vs baseline: 1.1475x; 1.1475x over previous
#include <cuda_runtime.h>
#include <cstdint>

#define CIN  32
#define COUT 64
#define KOFF 27

// ---------------------------------------------------------------------------
// R8 kernel VERBATIM (best measured: 696 us total, 73 us/launch).
// Fused gather -> per-pair 32x64 GEMM -> scatter-accumulate.
// Lane (h, j): h = c-half (c in [16h,16h+16)), j = channels 4j..4j+3.
//   stage  : cooperative gather (8 lanes per row -> 1 line per row).
//   math   : packed fma.rn.f32x2 against natural weight pairs (64 regs, no
//            spill); dup-MOVs amortized over 2 FMAs.
//   combine: shfl_xor(16) + add.rn.f32x2 merges the two c-halves.
//   scatter: one red.global.v4.f32 instr per 2 pairs.
// ---------------------------------------------------------------------------
__global__ __launch_bounds__(128, 4) void conv_scatter_kernel(
    const float* __restrict__ feats,
    const float* __restrict__ W,
    const int*   __restrict__ in_idx,
    const int*   __restrict__ out_idx,
    float*       __restrict__ out,
    int M, int kBase)
{
    __shared__ __align__(16) float4 rows[4][32][9];  // padded pitch

    const int k    = kBase + (int)blockIdx.y;
    const int warp = threadIdx.x >> 5;
    const int lane = threadIdx.x & 31;
    const int h    = lane >> 4;         // c-half: c in [16h, 16h+16)
    const int j    = lane & 15;         // channels 4j..4j+3

    // Natural-pair weight registers: w01[i]={W[16h+i][4j],W[..][4j+1]}, w23 hi.
    unsigned long long w01[16], w23[16];
    {
        const float* Wk = W + (size_t)k * (CIN * COUT) + 4 * j;
        #pragma unroll
        for (int i = 0; i < 16; ++i) {
            float4 v = *reinterpret_cast<const float4*>(Wk + (16 * h + i) * COUT);
            asm("mov.b64 %0, {%1, %2};" : "=l"(w01[i]) : "f"(v.x), "f"(v.y));
            asm("mov.b64 %0, {%1, %2};" : "=l"(w23[i]) : "f"(v.z), "f"(v.w));
        }
    }

    const int mBase = ((int)blockIdx.x * 4 + warp) * 32;
    if (mBase >= M) return;
    const int nt = (M - mBase < 32) ? (M - mBase) : 32;

    const size_t base = (size_t)k * M + mBase;
    int ikv = 0, okv = 0;
    if (lane < nt) {
        ikv = in_idx[base + lane];
        okv = out_idx[base + lane];
    }

    // Cooperative stage: iteration r loads rows 4r..4r+3; 8 lanes per row,
    // lane covers sector (lane&7) of row 4r+(lane>>3). One 128B line/row.
    {
        const float4* fb  = reinterpret_cast<const float4*>(feats);
        const int     g   = lane >> 3;
        const int     sec = lane & 7;
        #pragma unroll
        for (int r = 0; r < 8; ++r) {
            const int row = 4 * r + g;
            const int ik  = __shfl_sync(0xffffffffu, ikv, row);
            rows[warp][row][sec] = fb[(size_t)ik * 8 + sec];
        }
    }
    __syncwarp();

    #pragma unroll 1
    for (int t4 = 0; 4 * t4 < nt; ++t4) {
        unsigned long long a01[4] = {0ull, 0ull, 0ull, 0ull};
        unsigned long long a23[4] = {0ull, 0ull, 0ull, 0ull};

        #pragma unroll
        for (int p = 0; p < 4; ++p) {
            const float4* rp = rows[warp][4 * t4 + p];
            #pragma unroll
            for (int cc = 0; cc < 4; ++cc) {
                float4 v = rp[4 * h + cc];   // this half's 4 c-values
                unsigned long long d;
                asm("mov.b64 %0, {%1, %1};" : "=l"(d) : "f"(v.x));
                asm("fma.rn.f32x2 %0, %1, %2, %0;" : "+l"(a01[p]) : "l"(d), "l"(w01[4*cc+0]));
                asm("fma.rn.f32x2 %0, %1, %2, %0;" : "+l"(a23[p]) : "l"(d), "l"(w23[4*cc+0]));
                asm("mov.b64 %0, {%1, %1};" : "=l"(d) : "f"(v.y));
                asm("fma.rn.f32x2 %0, %1, %2, %0;" : "+l"(a01[p]) : "l"(d), "l"(w01[4*cc+1]));
                asm("fma.rn.f32x2 %0, %1, %2, %0;" : "+l"(a23[p]) : "l"(d), "l"(w23[4*cc+1]));
                asm("mov.b64 %0, {%1, %1};" : "=l"(d) : "f"(v.z));
                asm("fma.rn.f32x2 %0, %1, %2, %0;" : "+l"(a01[p]) : "l"(d), "l"(w01[4*cc+2]));
                asm("fma.rn.f32x2 %0, %1, %2, %0;" : "+l"(a23[p]) : "l"(d), "l"(w23[4*cc+2]));
                asm("mov.b64 %0, {%1, %1};" : "=l"(d) : "f"(v.w));
                asm("fma.rn.f32x2 %0, %1, %2, %0;" : "+l"(a01[p]) : "l"(d), "l"(w01[4*cc+3]));
                asm("fma.rn.f32x2 %0, %1, %2, %0;" : "+l"(a23[p]) : "l"(d), "l"(w23[4*cc+3]));
            }
        }

        // Combine c-halves: lane j <-> lane j+16 hold same (pairs, channels).
        #pragma unroll
        for (int p = 0; p < 4; ++p) {
            unsigned long long o1 = __shfl_xor_sync(0xffffffffu, a01[p], 16);
            unsigned long long o2 = __shfl_xor_sync(0xffffffffu, a23[p], 16);
            asm("add.rn.f32x2 %0, %0, %1;" : "+l"(a01[p]) : "l"(o1));
            asm("add.rn.f32x2 %0, %0, %1;" : "+l"(a23[p]) : "l"(o2));
        }

        // Scatter: group g covers pairs {2g, 2g+1}; half h writes pair 2g+h.
        #pragma unroll
        for (int g = 0; g < 2; ++g) {
            unsigned long long A = h ? a01[2 * g + 1] : a01[2 * g];
            unsigned long long B = h ? a23[2 * g + 1] : a23[2 * g];
            const int pr = 4 * t4 + 2 * g + h;
            const int ok = __shfl_sync(0xffffffffu, okv, pr);
            if (pr < nt) {
                float r0, r1, r2, r3;
                asm("mov.b64 {%0, %1}, %2;" : "=f"(r0), "=f"(r1) : "l"(A));
                asm("mov.b64 {%0, %1}, %2;" : "=f"(r2), "=f"(r3) : "l"(B));
                float* dst = out + (size_t)ok * COUT + 4 * j;
                asm volatile("red.global.v4.f32.add [%0], {%1, %2, %3, %4};"
                             :: "l"(dst), "f"(r0), "f"(r1), "f"(r2), "f"(r3) : "memory");
            }
        }
    }
}

// ---------------------------------------------------------------------------
// In-place BatchNorm (inference) + ReLU epilogue, vectorized float4.
// ---------------------------------------------------------------------------
__global__ __launch_bounds__(256) void bn_relu_kernel(
    float* __restrict__ out,
    const float* __restrict__ gamma,
    const float* __restrict__ beta,
    const float* __restrict__ run_mean,
    const float* __restrict__ run_var,
    int n4)
{
    int i = blockIdx.x * blockDim.x + threadIdx.x;
    if (i >= n4) return;

    const int c0 = (i & 15) * 4;
    float4 v = reinterpret_cast<float4*>(out)[i];

    float s0 = gamma[c0 + 0] * rsqrtf(run_var[c0 + 0] + 1e-5f);
    float s1 = gamma[c0 + 1] * rsqrtf(run_var[c0 + 1] + 1e-5f);
    float s2 = gamma[c0 + 2] * rsqrtf(run_var[c0 + 2] + 1e-5f);
    float s3 = gamma[c0 + 3] * rsqrtf(run_var[c0 + 3] + 1e-5f);

    float t0 = beta[c0 + 0] - run_mean[c0 + 0] * s0;
    float t1 = beta[c0 + 1] - run_mean[c0 + 1] * s1;
    float t2 = beta[c0 + 2] - run_mean[c0 + 2] * s2;
    float t3 = beta[c0 + 3] - run_mean[c0 + 3] * s3;

    v.x = fmaxf(fmaf(v.x, s0, t0), 0.0f);
    v.y = fmaxf(fmaf(v.y, s1, t1), 0.0f);
    v.z = fmaxf(fmaf(v.z, s2, t2), 0.0f);
    v.w = fmaxf(fmaf(v.w, s3, t3), 0.0f);

    reinterpret_cast<float4*>(out)[i] = v;
}

// ---------------------------------------------------------------------------
// Launcher: memset(zero) -> 3x conv (9 k-planes each: fewer launch tails
// than the 9x3 of the 696us run, kernel untouched) -> BN+ReLU.
// ncu profiled launch #5 = conv of call 2.
// ---------------------------------------------------------------------------
extern "C" void kernel_launch(void* const* d_in, const int* in_sizes, int n_in,
                              void* d_out, int out_size)
{
    const float* feats    = (const float*)d_in[0];
    const float* W        = (const float*)d_in[1];
    const float* gamma    = (const float*)d_in[2];
    const float* beta     = (const float*)d_in[3];
    const float* run_mean = (const float*)d_in[4];
    const float* run_var  = (const float*)d_in[5];
    const int*   in_idx   = (const int*)d_in[6];
    const int*   out_idx  = (const int*)d_in[7];
    float*       out      = (float*)d_out;

    const int KM = in_sizes[6];
    const int M  = KM / KOFF;

    cudaMemsetAsync(d_out, 0, (size_t)out_size * sizeof(float), 0);

    const int gx = (M + 127) / 128;
    for (int kb = 0; kb < KOFF; kb += 9) {
        dim3 grid(gx, 9);
        conv_scatter_kernel<<<grid, 128>>>(feats, W, in_idx, out_idx, out, M, kb);
    }

    const int n4 = out_size / 4;
    bn_relu_kernel<<<(n4 + 255) / 256, 256>>>(out, gamma, beta, run_mean, run_var, n4);
}